// round 13
// baseline (speedup 1.0000x reference)
#include <cuda_runtime.h>
#include <cstdint>

// Problem constants
#define NN      8192        // N edges
#define EE      256         // embedding dim
#define SS      16          // survival steps
#define NSRC    10000
#define MINDST  10000
#define SURV_ROWS  (SS * NN)            // 131072
#define TOTAL_ROWS (SURV_ROWS + NN)     // 139264 (surv rows + edge rows)

#define PRE_BLOCKS  256                 // 256 x 32 = 8192 edges, SM-spread
#define MAIN_BLOCKS 444                 // 3 blocks/SM x 148 SMs, single wave
#define TOTW        (MAIN_BLOCKS * 8)   // 3552 warps, ~39 rows each

// Scratch (no allocation allowed -> __device__ globals)
__device__ float  g_td_uv[NN];
__device__ int    g_as[NN];
__device__ int    g_ad[NN];
__device__ float  g_ua[NN];
__device__ int    g_accu_idx[NN];
__device__ double g_part_surv[MAIN_BLOCKS];
__device__ double g_part_lam[MAIN_BLOCKS];
__device__ double g_part_acc[MAIN_BLOCKS];
__device__ unsigned int g_done = 0;

__device__ __forceinline__ float hawkes(float dot, float td,
                                        float b, float psi, float alpha, float w_t)
{
    float g  = dot + b + alpha * expf(-w_t * td * (1.0f / 5000.0f));
    float gp = fminf(fmaxf(g / (psi + 1e-7f), -75.0f), 75.0f);
    return psi * (log1pf(expf(-gp)) + gp);
}

// ---------------------------------------------------------------------------
// Kernel 1 (tiny): resolves indirection chains only.
// ---------------------------------------------------------------------------
__global__ __launch_bounds__(32)
void pre_kernel(const int*   __restrict__ assoc,
                const int*   __restrict__ src,
                const int*   __restrict__ dst,
                const float* __restrict__ last_update,
                const float* __restrict__ cur_time,
                const float* __restrict__ last_time_pos)
{
    int e = blockIdx.x * 32 + threadIdx.x;       // always < NN
    int   s   = src[e];
    int   d   = dst[e];
    int   as  = assoc[s];
    int   ad  = assoc[d];
    float lu  = fmaxf(last_update[as], last_update[ad]);
    float ltp = last_time_pos[e];

    g_td_uv[e]    = cur_time[e] - fmaxf(lu, ltp);
    g_as[e]       = as;
    g_ad[e]       = ad;
    g_ua[e]       = (ltp >= lu) ? 1.0f : 0.0f;
    g_accu_idx[e] = s * NSRC + (d - MINDST);
}

// ---------------------------------------------------------------------------
// cp.async helpers
// ---------------------------------------------------------------------------
#define CPA(saddr, gptr)                                                     \
    asm volatile("cp.async.cg.shared.global [%0], [%1], 16;\n"               \
                 :: "r"(saddr), "l"(gptr))
#define CPA_COMMIT() asm volatile("cp.async.commit_group;\n" ::: "memory")
#define CPA_WAIT(n)  asm volatile("cp.async.wait_group %0;\n" :: "n"(n) : "memory")

// ---------------------------------------------------------------------------
// Kernel 2: unified persistent streaming kernel, cp.async 3-stage smem ring.
//  - warp-per-row, 3 stages x 2KB per warp (48KB static smem/block)
//  - consume row k while rows k+1, k+2 stream into smem (per-thread
//    wait_group; each lane reads only bytes it copied itself)
//  - rows [0, SURV_ROWS): survival rows; [SURV_ROWS, TOTAL): edge rows
//  - threads gtid < NN also hide one random accu gather
//  - last-done block performs the deterministic final reduction -> out
// ---------------------------------------------------------------------------
__global__ __launch_bounds__(256, 3)
void main_kernel(const float* __restrict__ u,
                 const float* __restrict__ v,
                 const float* __restrict__ tdstep,
                 const float* __restrict__ emb,
                 const float* __restrict__ accu,
                 const float* __restrict__ W,
                 const float* __restrict__ b_,
                 const float* __restrict__ psi_,
                 const float* __restrict__ alpha_,
                 const float* __restrict__ wt_,
                 float* __restrict__ out)
{
    // 8 warps x 3 stages x 128 float4 (2KB) = 49152 B exactly
    __shared__ __align__(16) float4 sbuf[8][3][128];

    const int tid = threadIdx.x, warp = tid >> 5, lane = tid & 31;

    // W in registers: lane owns float4s {lane, 32+lane} of Wu and
    // {64+lane, 96+lane} of Wv. 4 float4 = 16 regs.
    const float4* w4 = (const float4*)W;
    const float4 wu0 = w4[lane];
    const float4 wu1 = w4[32 + lane];
    const float4 wv0 = w4[64 + lane];
    const float4 wv1 = w4[96 + lane];

    const float b     = b_[0];
    const float psi   = psi_[0];
    const float alpha = alpha_[0];
    const float wt    = wt_[0];

    double acc_s = 0.0;   // sum lambda_surv * td_uv      (lane 0)
    double acc_l = 0.0;   // sum -log(lambda_uv + 1e-7)   (lane 0)
    double acc_a = 0.0;   // sum use_accu * accu[...]     (all lanes)

    // Hidden random gather: one accu element per early global thread.
    int gtid = blockIdx.x * 256 + tid;
    if (gtid < NN)
        acc_a = (double)(g_ua[gtid] * __ldg(&accu[g_accu_idx[gtid]]));

    const float4* u4 = (const float4*)u;
    const float4* v4 = (const float4*)v;
    const float4* e4 = (const float4*)emb;

    const uint32_t sb =
        (uint32_t)__cvta_generic_to_shared(&sbuf[warp][0][0]) + lane * 16u;

    // Issue row R's 4 cp.asyncs into stage ST, record metadata.
#define ISSUE(ST, R, TDU, TD, SV)                                            \
    do {                                                                     \
        int _r = (R);                                                        \
        const float4 *_pu, *_pv;                                             \
        (SV) = (_r < SURV_ROWS);                                             \
        if (SV) {                                                            \
            _pu = u4 + (size_t)_r * 64;                                      \
            _pv = v4 + (size_t)_r * 64;                                      \
            (TDU) = g_td_uv[_r & (NN - 1)];                                  \
            (TD)  = tdstep[_r] * (TDU);                                      \
        } else {                                                             \
            int _e = _r - SURV_ROWS;                                         \
            _pu = e4 + (size_t)g_as[_e] * 64;                                \
            _pv = e4 + (size_t)g_ad[_e] * 64;                                \
            (TDU) = 0.f;                                                     \
            (TD)  = g_td_uv[_e];                                             \
        }                                                                    \
        uint32_t _s = sb + (ST) * 2048u;                                     \
        CPA(_s,         _pu + lane);                                         \
        CPA(_s + 512u,  _pu + 32 + lane);                                    \
        CPA(_s + 1024u, _pv + lane);                                         \
        CPA(_s + 1536u, _pv + 32 + lane);                                    \
    } while (0)

    // Consume stage ST (data guaranteed arrived by caller's wait_group).
#define CONSUME(ST, TDU, TD, SV)                                             \
    do {                                                                     \
        const float4* _sp = &sbuf[warp][ST][0];                              \
        float4 _a0 = _sp[lane];                                              \
        float4 _a1 = _sp[32 + lane];                                         \
        float4 _c0 = _sp[64 + lane];                                         \
        float4 _c1 = _sp[96 + lane];                                         \
        float _dot = _a0.x * wu0.x + _a0.y * wu0.y + _a0.z * wu0.z           \
                   + _a0.w * wu0.w                                           \
                   + _a1.x * wu1.x + _a1.y * wu1.y + _a1.z * wu1.z           \
                   + _a1.w * wu1.w                                           \
                   + _c0.x * wv0.x + _c0.y * wv0.y + _c0.z * wv0.z           \
                   + _c0.w * wv0.w                                           \
                   + _c1.x * wv1.x + _c1.y * wv1.y + _c1.z * wv1.z           \
                   + _c1.w * wv1.w;                                          \
        _Pragma("unroll")                                                    \
        for (int _o = 16; _o; _o >>= 1)                                      \
            _dot += __shfl_xor_sync(0xffffffffu, _dot, _o);                  \
        if (lane == 0) {                                                     \
            float _lam = hawkes(_dot, (TD), b, psi, alpha, wt);              \
            if (SV) acc_s += (double)_lam * (double)(TDU);                   \
            else    acc_l -= (double)logf(_lam + 1e-7f);                     \
        }                                                                    \
    } while (0)

    // --- pipeline ---------------------------------------------------------
    float tdu0, td0, tdu1, td1, tdu2, td2;
    bool  sv0, sv1, sv2;
    bool  v0 = false, v1 = false, v2 = false;

    int gw   = blockIdx.x * 8 + warp;
    int last = gw - TOTW;                 // last issued row

    {   // prologue: fill up to 3 stages (always 3 commits)
        int r = last + TOTW;
        v0 = (r < TOTAL_ROWS);
        if (v0) { ISSUE(0, r, tdu0, td0, sv0); last = r; }
        CPA_COMMIT();
        r = last + TOTW;
        v1 = v0 && (r < TOTAL_ROWS);
        if (v1) { ISSUE(1, r, tdu1, td1, sv1); last = r; }
        CPA_COMMIT();
        r = last + TOTW;
        v2 = v1 && (r < TOTAL_ROWS);
        if (v2) { ISSUE(2, r, tdu2, td2, sv2); last = r; }
        CPA_COMMIT();
    }

    for (;;) {
        if (!v0) break;
        CPA_WAIT(2);
        CONSUME(0, tdu0, td0, sv0);
        { int r = last + TOTW; v0 = (r < TOTAL_ROWS);
          if (v0) { ISSUE(0, r, tdu0, td0, sv0); last = r; } }
        CPA_COMMIT();

        if (!v1) break;
        CPA_WAIT(2);
        CONSUME(1, tdu1, td1, sv1);
        { int r = last + TOTW; v1 = (r < TOTAL_ROWS);
          if (v1) { ISSUE(1, r, tdu1, td1, sv1); last = r; } }
        CPA_COMMIT();

        if (!v2) break;
        CPA_WAIT(2);
        CONSUME(2, tdu2, td2, sv2);
        { int r = last + TOTW; v2 = (r < TOTAL_ROWS);
          if (v2) { ISSUE(2, r, tdu2, td2, sv2); last = r; } }
        CPA_COMMIT();
    }

    // epilogue: drain pending stages (fixed, input-independent slot order ->
    // deterministic double accumulation)
    CPA_WAIT(0);
    if (v0) CONSUME(0, tdu0, td0, sv0);
    if (v1) CONSUME(1, tdu1, td1, sv1);
    if (v2) CONSUME(2, tdu2, td2, sv2);

#undef ISSUE
#undef CONSUME

    // Warp reduce accu partial (fixed butterfly -> deterministic).
#pragma unroll
    for (int o = 16; o; o >>= 1)
        acc_a += __shfl_xor_sync(0xffffffffu, acc_a, o);

    // -- block combine; smem ring is dead now, reuse it ---------------------
    __syncthreads();
    double* shd  = (double*)&sbuf[0][0][0];   // reuse: [0..7]=ssv [8..15]=slm
    double* ssv  = shd;                       //        [16..23]=sac
    double* slm  = shd + 8;                   //        [24..279]=sh[256]
    double* sh   = shd + 24;
    int*    flag = (int*)(shd + 280);

    if (lane == 0) { ssv[warp] = acc_s; slm[warp] = acc_l; (shd + 16)[warp] = acc_a; }
    __syncthreads();
    if (tid == 0) {
        double a = 0.0, c = 0.0, q = 0.0;
#pragma unroll
        for (int k = 0; k < 8; k++) { a += ssv[k]; c += slm[k]; q += (shd + 16)[k]; }
        g_part_surv[blockIdx.x] = a;
        g_part_lam[blockIdx.x]  = c;
        g_part_acc[blockIdx.x]  = q;
        __threadfence();
        unsigned int prev = atomicAdd(&g_done, 1u);
        flag[0] = (prev == MAIN_BLOCKS - 1) ? 1 : 0;
    }
    __syncthreads();

    if (flag[0]) {
        double s = 0.0;
        for (int j = tid; j < MAIN_BLOCKS; j += 256) s += g_part_surv[j];
        sh[tid] = s; __syncthreads();
        for (int o = 128; o; o >>= 1) { if (tid < o) sh[tid] += sh[tid + o]; __syncthreads(); }
        double surv = sh[0]; __syncthreads();

        double l = 0.0;
        for (int j = tid; j < MAIN_BLOCKS; j += 256) l += g_part_lam[j];
        sh[tid] = l; __syncthreads();
        for (int o = 128; o; o >>= 1) { if (tid < o) sh[tid] += sh[tid + o]; __syncthreads(); }
        double lam = sh[0]; __syncthreads();

        double q = 0.0;
        for (int j = tid; j < MAIN_BLOCKS; j += 256) q += g_part_acc[j];
        sh[tid] = q; __syncthreads();
        for (int o = 128; o; o >>= 1) { if (tid < o) sh[tid] += sh[tid + o]; __syncthreads(); }

        if (tid == 0) {
            out[0] = (float)(lam / (double)NN);
            out[1] = (float)((surv / (double)SS + sh[0]) / (double)NN);
            g_done = 0;   // reset for next graph replay
        }
    }
}

// ---------------------------------------------------------------------------
// Inputs (metadata order):
//  0 all_embeddings (20000,256) f32   1 assoc (20000,) i32
//  2 src (8192,) i32                  3 pos_dst (8192,) i32
//  4 last_update (20000,) f32         5 cur_time (8192,) f32
//  6 u_non_embeddings (131072,256)    7 v_non_embeddings (131072,256)
//  8 last_time_pos (8192,) f32        9 td_surv_step (16,8192) f32
// 10 event_inten_accu (10000,10000)  11 W_omega (1,512)
// 12 b_omega (1,)  13 psi (1,)  14 alpha (1,)  15 w_t (1,)
// ---------------------------------------------------------------------------
extern "C" void kernel_launch(void* const* d_in, const int* in_sizes, int n_in,
                              void* d_out, int out_size)
{
    const float* emb     = (const float*)d_in[0];
    const int*   assoc   = (const int*)  d_in[1];
    const int*   src     = (const int*)  d_in[2];
    const int*   dst     = (const int*)  d_in[3];
    const float* lupd    = (const float*)d_in[4];
    const float* ctime   = (const float*)d_in[5];
    const float* u_non   = (const float*)d_in[6];
    const float* v_non   = (const float*)d_in[7];
    const float* ltp     = (const float*)d_in[8];
    const float* tdstep  = (const float*)d_in[9];
    const float* accu    = (const float*)d_in[10];
    const float* W       = (const float*)d_in[11];
    const float* b       = (const float*)d_in[12];
    const float* psi     = (const float*)d_in[13];
    const float* alpha   = (const float*)d_in[14];
    const float* w_t     = (const float*)d_in[15];
    float* out = (float*)d_out;

    pre_kernel<<<PRE_BLOCKS, 32>>>(assoc, src, dst, lupd, ctime, ltp);
    main_kernel<<<MAIN_BLOCKS, 256>>>(u_non, v_non, tdstep, emb, accu, W,
                                      b, psi, alpha, w_t, out);
}